// round 2
// baseline (speedup 1.0000x reference)
#include <cuda_runtime.h>
#include <math.h>

// Problem constants
#define NB    64
#define NPOMO 200
#define NPROB 200
#define NEMB  512
#define NHEAD 16
#define NHD   32
#define NNODE 201   // PROB + 1

// ---------------- scratch (device globals; no runtime allocation) -----------
static __device__ float g_kbuf[(size_t)NB * NNODE * NEMB];          // 26.3 MB
static __device__ float g_vbuf[(size_t)NB * NNODE * NEMB];          // 26.3 MB
static __device__ float g_qbuf[(size_t)NB * NPOMO * NEMB];          // 26.2 MB
static __device__ float g_sbuf[(size_t)NB * NHEAD * NPOMO * NNODE]; // 164.7 MB
static __device__ float g_obuf[(size_t)NB * NPOMO * NEMB];          // 26.2 MB
static __device__ float g_mhbuf[(size_t)NB * NPOMO * NEMB];         // 26.2 MB

// ---------------- generic batched GEMM ---------------------------------------
// C[z] = epilogue( alpha * (A[z] @ B[z]  (+ A2[z] @ B2[z])) )
// z = zb * nbH + zh; per-operand strides for zb and zh.
// transB: B is stored (N x K) row-major, we need B[k][n] = Bst[n][k].
// epMode: 0 none, 1 +bias[col], 2 10*tanh(v)+mask, 3 v+mask
#define BMT 64
#define BNT 128
#define BKT 16

__global__ __launch_bounds__(256)
void gemm_kernel(const float* __restrict__ A0, const float* __restrict__ B0,
                 const float* __restrict__ A1p, const float* __restrict__ B1p,
                 const float* __restrict__ bias, const float* __restrict__ mask,
                 float* __restrict__ C,
                 int M, int N, int K,
                 int lda, int ldb, int ldc,
                 long long aSb, long long aSh,
                 long long bSb, long long bSh,
                 long long cSb, long long cSh,
                 long long mSb,
                 int nbH, int transB, int epMode, int maskCols, float alpha)
{
    __shared__ float sA[BKT][BMT];
    __shared__ float sB[BKT][BNT];

    const int t  = threadIdx.x;
    const int zb = blockIdx.z / nbH;
    const int zh = blockIdx.z - zb * nbH;
    const int m0 = blockIdx.y * BMT;
    const int n0 = blockIdx.x * BNT;

    const long long aOff = (long long)zb * aSb + (long long)zh * aSh;
    const long long bOff = (long long)zb * bSb + (long long)zh * bSh;
    float* Cp = C + (long long)zb * cSb + (long long)zh * cSh;
    const float* Mp = mask ? (mask + (long long)zb * mSb) : nullptr;

    float acc[4][8];
#pragma unroll
    for (int i = 0; i < 4; i++)
#pragma unroll
        for (int j = 0; j < 8; j++) acc[i][j] = 0.0f;

    const int ty = t >> 4;   // 0..15 -> rows ty*4..+3
    const int tx = t & 15;   // 0..15 -> cols tx*8..+7

    const int nsrc = (A1p != nullptr) ? 2 : 1;

    for (int src = 0; src < nsrc; src++) {
        const float* Ap = (src ? A1p : A0) + aOff;
        const float* Bp = (src ? B1p : B0) + bOff;

        for (int k0 = 0; k0 < K; k0 += BKT) {
            // ---- load A tile (BM x BK), store k-major ----
            {
                const int mloc = t >> 2;
                const int kg   = (t & 3) * 4;
                const int row  = m0 + mloc;
#pragma unroll
                for (int j = 0; j < 4; j++) {
                    const int kk = k0 + kg + j;
                    float v = 0.0f;
                    if (row < M && kk < K) v = Ap[(long long)row * lda + kk];
                    sA[kg + j][mloc] = v;
                }
            }
            // ---- load B tile (BK x BN) ----
            if (!transB) {
                const int kloc = t >> 4;
                const int ng   = (t & 15) * 8;
                const int kk   = k0 + kloc;
#pragma unroll
                for (int j = 0; j < 8; j++) {
                    const int col = n0 + ng + j;
                    float v = 0.0f;
                    if (kk < K && col < N) v = Bp[(long long)kk * ldb + col];
                    sB[kloc][ng + j] = v;
                }
            } else {
                const int nloc = t >> 1;
                const int kg   = (t & 1) * 8;
                const int col  = n0 + nloc;
#pragma unroll
                for (int j = 0; j < 8; j++) {
                    const int kk = k0 + kg + j;
                    float v = 0.0f;
                    if (col < N && kk < K) v = Bp[(long long)col * ldb + kk];
                    sB[kg + j][nloc] = v;
                }
            }
            __syncthreads();

#pragma unroll
            for (int kk = 0; kk < BKT; kk++) {
                const float4 a4  = *(const float4*)&sA[kk][ty * 4];
                const float4 b4a = *(const float4*)&sB[kk][tx * 8];
                const float4 b4b = *(const float4*)&sB[kk][tx * 8 + 4];
                const float a[4] = {a4.x, a4.y, a4.z, a4.w};
                const float b[8] = {b4a.x, b4a.y, b4a.z, b4a.w,
                                    b4b.x, b4b.y, b4b.z, b4b.w};
#pragma unroll
                for (int i = 0; i < 4; i++)
#pragma unroll
                    for (int j = 0; j < 8; j++)
                        acc[i][j] = fmaf(a[i], b[j], acc[i][j]);
            }
            __syncthreads();
        }
    }

    // ---- epilogue ----
#pragma unroll
    for (int i = 0; i < 4; i++) {
        const int row = m0 + ty * 4 + i;
        if (row >= M) continue;
#pragma unroll
        for (int j = 0; j < 8; j++) {
            const int col = n0 + tx * 8 + j;
            if (col >= N) continue;
            float v = acc[i][j] * alpha;
            if (epMode == 1) {
                v += bias[col];
            } else if (epMode == 2) {
                v = 10.0f * tanhf(v);
                if (col < maskCols) v += Mp[(long long)row * maskCols + col];
            } else if (epMode == 3) {
                if (col < maskCols) v += Mp[(long long)row * maskCols + col];
            }
            Cp[(long long)row * ldc + col] = v;
        }
    }
}

// ---------------- row softmax (in place), warp per row ----------------------
__global__ __launch_bounds__(256)
void softmax_kernel(float* __restrict__ X, int rows, int L)
{
    const int gwarp = (blockIdx.x * blockDim.x + threadIdx.x) >> 5;
    const int lane  = threadIdx.x & 31;
    if (gwarp >= rows) return;
    float* rowp = X + (long long)gwarp * L;

    float vals[7];
    float mx = -INFINITY;
#pragma unroll
    for (int i = 0; i < 7; i++) {
        const int idx = lane + i * 32;
        const float v = (idx < L) ? rowp[idx] : -INFINITY;
        vals[i] = v;
        mx = fmaxf(mx, v);
    }
#pragma unroll
    for (int o = 16; o > 0; o >>= 1) mx = fmaxf(mx, __shfl_xor_sync(0xffffffffu, mx, o));

    float sum = 0.0f;
#pragma unroll
    for (int i = 0; i < 7; i++) {
        const int idx = lane + i * 32;
        const float e = (idx < L) ? expf(vals[i] - mx) : 0.0f;
        vals[i] = e;
        sum += e;
    }
#pragma unroll
    for (int o = 16; o > 0; o >>= 1) sum += __shfl_xor_sync(0xffffffffu, sum, o);

    const float inv = 1.0f / sum;
#pragma unroll
    for (int i = 0; i < 7; i++) {
        const int idx = lane + i * 32;
        if (idx < L) rowp[idx] = vals[i] * inv;
    }
}

// ---------------- launch ------------------------------------------------------
static inline int cdiv(int a, int b) { return (a + b - 1) / b; }

extern "C" void kernel_launch(void* const* d_in, const int* in_sizes, int n_in,
                              void* d_out, int out_size)
{
    const float* nodes = (const float*)d_in[0];  // (64, 201, 512)
    const float* q1    = (const float*)d_in[1];  // (64, 200, 512)
    const float* lastn = (const float*)d_in[2];  // (64, 200, 512)
    const float* ninf  = (const float*)d_in[3];  // (64, 200, 200)
    const float* Wqf   = (const float*)d_in[4];  // (512, 512)
    const float* Wql   = (const float*)d_in[5];
    const float* Wk    = (const float*)d_in[6];
    const float* Wv    = (const float*)d_in[7];
    const float* Wc    = (const float*)d_in[8];
    const float* bc    = (const float*)d_in[9];  // (512,)
    float* out = (float*)d_out;                  // (64, 200, 200)

    float *kbuf, *vbuf, *qbuf, *sbuf, *obuf, *mhbuf;
    cudaGetSymbolAddress((void**)&kbuf,  g_kbuf);
    cudaGetSymbolAddress((void**)&vbuf,  g_vbuf);
    cudaGetSymbolAddress((void**)&qbuf,  g_qbuf);
    cudaGetSymbolAddress((void**)&sbuf,  g_sbuf);
    cudaGetSymbolAddress((void**)&obuf,  g_obuf);
    cudaGetSymbolAddress((void**)&mhbuf, g_mhbuf);

    const dim3 blk(256);
    const float inv_sqrt_d   = 0.17677669529663687f;   // 1/sqrt(32)
    const float inv_sqrt_emb = 0.04419417382415922f;   // 1/22.627416997969522

    const int Mn = NB * NNODE;   // 12864
    const int Mq = NB * NPOMO;   // 12800

    // 1) K projection: kbuf = nodes @ Wk        (12864 x 512 x 512)
    gemm_kernel<<<dim3(cdiv(NEMB, BNT), cdiv(Mn, BMT), 1), blk>>>(
        nodes, Wk, nullptr, nullptr, nullptr, nullptr, kbuf,
        Mn, NEMB, NEMB, NEMB, NEMB, NEMB,
        0, 0, 0, 0, 0, 0, 0,
        1, 0, 0, 0, 1.0f);

    // 2) V projection
    gemm_kernel<<<dim3(cdiv(NEMB, BNT), cdiv(Mn, BMT), 1), blk>>>(
        nodes, Wv, nullptr, nullptr, nullptr, nullptr, vbuf,
        Mn, NEMB, NEMB, NEMB, NEMB, NEMB,
        0, 0, 0, 0, 0, 0, 0,
        1, 0, 0, 0, 1.0f);

    // 3) Q projection (fused dual GEMM): qbuf = q1@Wqf + lastn@Wql
    gemm_kernel<<<dim3(cdiv(NEMB, BNT), cdiv(Mq, BMT), 1), blk>>>(
        q1, Wqf, lastn, Wql, nullptr, nullptr, qbuf,
        Mq, NEMB, NEMB, NEMB, NEMB, NEMB,
        0, 0, 0, 0, 0, 0, 0,
        1, 0, 0, 0, 1.0f);

    // 4) attention scores per (b,h): S = Q @ K^T / sqrt(D) + mask3
    //    A = qbuf[b, :, h*32:(h+1)*32] (200 x 32, lda 512)
    //    B = kbuf[b, :, h*32:(h+1)*32] (201 x 32, transB)
    //    C = sbuf[(b*16+h)] (200 x 201)
    gemm_kernel<<<dim3(cdiv(NNODE, BNT), cdiv(NPOMO, BMT), NB * NHEAD), blk>>>(
        qbuf, kbuf, nullptr, nullptr, nullptr, ninf, sbuf,
        NPOMO, NNODE, NHD, NEMB, NEMB, NNODE,
        (long long)NPOMO * NEMB, NHD,
        (long long)NNODE * NEMB, NHD,
        (long long)NHEAD * NPOMO * NNODE, (long long)NPOMO * NNODE,
        (long long)NPOMO * NPROB,
        NHEAD, 1, 3, NPROB, inv_sqrt_d);

    // 5) softmax over m (201) for 64*16*200 rows
    {
        const int rows = NB * NHEAD * NPOMO;
        softmax_kernel<<<cdiv(rows, 8), blk>>>(sbuf, rows, NNODE);
    }

    // 6) O = S @ V per (b,h): (200 x 32, K=201), written interleaved into obuf
    gemm_kernel<<<dim3(cdiv(NHD, BNT), cdiv(NPOMO, BMT), NB * NHEAD), blk>>>(
        sbuf, vbuf, nullptr, nullptr, nullptr, nullptr, obuf,
        NPOMO, NHD, NNODE, NNODE, NEMB, NEMB,
        (long long)NHEAD * NPOMO * NNODE, (long long)NPOMO * NNODE,
        (long long)NNODE * NEMB, NHD,
        (long long)NPOMO * NEMB, NHD,
        0,
        NHEAD, 0, 0, 0, 1.0f);

    // 7) mh = obuf @ Wc + bc   (12800 x 512 x 512)
    gemm_kernel<<<dim3(cdiv(NEMB, BNT), cdiv(Mq, BMT), 1), blk>>>(
        obuf, Wc, nullptr, nullptr, bc, nullptr, mhbuf,
        Mq, NEMB, NEMB, NEMB, NEMB, NEMB,
        0, 0, 0, 0, 0, 0, 0,
        1, 0, 1, 0, 1.0f);

    // 8) score2 per b: out = 10*tanh(mh @ nodes[:,:200]^T / sqrt(EMB)) + ninf
    gemm_kernel<<<dim3(cdiv(NPROB, BNT), cdiv(NPOMO, BMT), NB), blk>>>(
        mhbuf, nodes, nullptr, nullptr, nullptr, ninf, out,
        NPOMO, NPROB, NEMB, NEMB, NEMB, NPROB,
        (long long)NPOMO * NEMB, 0,
        (long long)NNODE * NEMB, 0,
        (long long)NPOMO * NPROB, 0,
        (long long)NPOMO * NPROB,
        1, 1, 2, NPROB, inv_sqrt_emb);

    // 9) final softmax over p (200) for 64*200 rows, in place on out
    {
        const int rows = NB * NPOMO;
        softmax_kernel<<<cdiv(rows, 8), blk>>>(out, rows, NPROB);
    }
}